// round 1
// baseline (speedup 1.0000x reference)
#include <cuda_runtime.h>
#include <math.h>

#define BATCH 4
#define SEQ   2048
#define DIM   128
#define ROWS  (BATCH*SEQ)   // 8192

// ---------------- scratch (no allocation allowed) ----------------
__device__ float g_q[ROWS*DIM];
__device__ float g_k[ROWS*DIM];
__device__ float g_v[ROWS*DIM];
__device__ float g_u[ROWS*2*DIM];
__device__ float g_sattn[ROWS*DIM];
__device__ float g_pattn[ROWS*DIM];
__device__ float g_g[ROWS*2*DIM];

__device__ __forceinline__ float silu_f(float v) { return v / (1.f + expf(-v)); }

// ---------------- kernel 1: fused q/k/v/u projections ----------------
// x[8192,128] @ {Wq,Wk,Wv:[128,128], Wu:[128,256]}; silu on q,k,v.
// grid (10, 128) : blockIdx.x -> 64-wide column tile of the virtual [*,640] output
__global__ void proj_kernel(const float* __restrict__ x,
                            const float* __restrict__ Wq, const float* __restrict__ bq,
                            const float* __restrict__ Wk, const float* __restrict__ bk,
                            const float* __restrict__ Wv, const float* __restrict__ bv,
                            const float* __restrict__ Wu, const float* __restrict__ bu)
{
    __shared__ float xs[64][33];
    __shared__ float ws[32][65];
    const int gc0 = blockIdx.x * 64;
    const int r0  = blockIdx.y * 64;

    const float* W; const float* bias; float* out; int ldw; int c0; bool act;
    if (gc0 < 128)      { W = Wq; bias = bq; out = g_q; ldw = 128; c0 = gc0;       act = true;  }
    else if (gc0 < 256) { W = Wk; bias = bk; out = g_k; ldw = 128; c0 = gc0 - 128; act = true;  }
    else if (gc0 < 384) { W = Wv; bias = bv; out = g_v; ldw = 128; c0 = gc0 - 256; act = true;  }
    else                { W = Wu; bias = bu; out = g_u; ldw = 256; c0 = gc0 - 384; act = false; }

    const int t = threadIdx.x, tx = t & 15, ty = t >> 4;
    float acc[4][4] = {};

    for (int kc = 0; kc < 128; kc += 32) {
        #pragma unroll
        for (int i = t; i < 64*32; i += 256) {
            int rr = i >> 5, cc = i & 31;
            xs[rr][cc] = x[(r0 + rr) * 128 + kc + cc];
        }
        #pragma unroll
        for (int i = t; i < 32*64; i += 256) {
            int rr = i >> 6, cc = i & 63;
            ws[rr][cc] = W[(kc + rr) * ldw + c0 + cc];
        }
        __syncthreads();
        #pragma unroll
        for (int kk = 0; kk < 32; kk++) {
            float av[4], bv2[4];
            #pragma unroll
            for (int i = 0; i < 4; i++) av[i] = xs[ty*4 + i][kk];
            #pragma unroll
            for (int j = 0; j < 4; j++) bv2[j] = ws[kk][tx*4 + j];
            #pragma unroll
            for (int i = 0; i < 4; i++)
                #pragma unroll
                for (int j = 0; j < 4; j++)
                    acc[i][j] = fmaf(av[i], bv2[j], acc[i][j]);
        }
        __syncthreads();
    }

    #pragma unroll
    for (int i = 0; i < 4; i++) {
        int rr = r0 + ty*4 + i;
        #pragma unroll
        for (int j = 0; j < 4; j++) {
            int cc = c0 + tx*4 + j;
            float v = acc[i][j] + bias[cc];
            if (act) v = silu_f(v);
            out[rr * ldw + cc] = v;
        }
    }
}

// ---------------- kernel 2: causal attention with silu(masked s^2) ----------------
// grid (S/64=32, B*H=16), 256 threads
__global__ void attn_kernel()
{
    __shared__ float qs[64][33];
    __shared__ float ks[64][33];
    __shared__ float vs[64][33];
    __shared__ float ss[64][65];

    const int n0 = blockIdx.x * 64;
    const int b  = blockIdx.y >> 2;
    const int h  = blockIdx.y & 3;
    const int t  = threadIdx.x;
    const int tx = t & 15, ty = t >> 4;
    const int col = t & 31, rgrp = t >> 5;     // out: col + rows rgrp*8..+7

    const float* qp = g_q + (size_t)(b * SEQ) * 128 + h * 32;
    const float* kp = g_k + (size_t)(b * SEQ) * 128 + h * 32;
    const float* vp = g_v + (size_t)(b * SEQ) * 128 + h * 32;
    const float scale = 0.17677669529663687f;  // 1/sqrt(32)

    #pragma unroll
    for (int i = t; i < 64*32; i += 256) {
        int rr = i >> 5, cc = i & 31;
        qs[rr][cc] = qp[(n0 + rr) * 128 + cc];
    }

    float acc[8] = {};

    for (int m0 = 0; m0 <= n0; m0 += 64) {
        #pragma unroll
        for (int i = t; i < 64*32; i += 256) {
            int rr = i >> 5, cc = i & 31;
            ks[rr][cc] = kp[(m0 + rr) * 128 + cc];
            vs[rr][cc] = vp[(m0 + rr) * 128 + cc];
        }
        __syncthreads();

        float sacc[4][4] = {};
        #pragma unroll
        for (int kk = 0; kk < 32; kk++) {
            float av[4], bv2[4];
            #pragma unroll
            for (int i = 0; i < 4; i++) av[i] = qs[ty*4 + i][kk];
            #pragma unroll
            for (int j = 0; j < 4; j++) bv2[j] = ks[tx*4 + j][kk];
            #pragma unroll
            for (int i = 0; i < 4; i++)
                #pragma unroll
                for (int j = 0; j < 4; j++)
                    sacc[i][j] = fmaf(av[i], bv2[j], sacc[i][j]);
        }
        #pragma unroll
        for (int i = 0; i < 4; i++) {
            int n = n0 + ty*4 + i;
            #pragma unroll
            for (int j = 0; j < 4; j++) {
                int m = m0 + tx*4 + j;
                float s  = sacc[i][j] * scale;
                float sq = (m <= n) ? s * s : 0.f;
                ss[ty*4 + i][tx*4 + j] = silu_f(sq);
            }
        }
        __syncthreads();

        #pragma unroll
        for (int j = 0; j < 8; j++) {
            int r = rgrp * 8 + j;
            float a = acc[j];
            #pragma unroll 8
            for (int m = 0; m < 64; m++)
                a = fmaf(ss[r][m], vs[m][col], a);
            acc[j] = a;
        }
        __syncthreads();
    }

    #pragma unroll
    for (int j = 0; j < 8; j++) {
        int r = n0 + rgrp * 8 + j;
        g_sattn[(size_t)(b * SEQ + r) * 128 + h * 32 + col] = acc[j];
    }
}

// ---------------- kernel 3: relative-position attention (banded Toeplitz GEMM) ----------------
// pos_attn[b,n,d] = sum_m pos_w[S-1+m-n] * v[b,m,d]
// grid (32, 2, 4) : n-tile 64, d-tile 64, batch
__global__ void pos_kernel(const float* __restrict__ pos_w)
{
    __shared__ float vs[64][65];
    __shared__ float sw[128];

    const int n0 = blockIdx.x * 64;
    const int d0 = blockIdx.y * 64;
    const int b  = blockIdx.z;
    const int t  = threadIdx.x, tx = t & 15, ty = t >> 4;

    float acc[4][4] = {};

    for (int m0 = 0; m0 < SEQ; m0 += 64) {
        #pragma unroll
        for (int i = t; i < 64*64; i += 256) {
            int rr = i >> 6, cc = i & 63;
            vs[rr][cc] = g_v[(size_t)(b * SEQ + m0 + rr) * 128 + d0 + cc];
        }
        if (t < 127) sw[t] = pos_w[(SEQ - 1) + m0 - n0 - 63 + t];
        __syncthreads();

        #pragma unroll 4
        for (int j = 0; j < 64; j++) {
            float vv[4];
            #pragma unroll
            for (int c = 0; c < 4; c++) vv[c] = vs[j][tx*4 + c];
            #pragma unroll
            for (int a = 0; a < 4; a++) {
                float w = sw[j - (ty*4 + a) + 63];
                #pragma unroll
                for (int c = 0; c < 4; c++)
                    acc[a][c] = fmaf(w, vv[c], acc[a][c]);
            }
        }
        __syncthreads();
    }

    #pragma unroll
    for (int a = 0; a < 4; a++) {
        int n = n0 + ty*4 + a;
        #pragma unroll
        for (int c = 0; c < 4; c++)
            g_pattn[(size_t)(b * SEQ + n) * 128 + d0 + tx*4 + c] = acc[a][c];
    }
}

// ---------------- kernel 4: LayerNorm(concat) * gamma + beta, times u ----------------
// one block (256 threads) per row
__global__ void ln_kernel(const float* __restrict__ gamma, const float* __restrict__ beta)
{
    const int row = blockIdx.x;
    const int t   = threadIdx.x;

    float a = (t < 128) ? g_sattn[(size_t)row * 128 + t]
                        : g_pattn[(size_t)row * 128 + (t - 128)];

    __shared__ float red[8];
    // mean
    float s = a;
    #pragma unroll
    for (int o = 16; o > 0; o >>= 1) s += __shfl_xor_sync(0xffffffffu, s, o);
    if ((t & 31) == 0) red[t >> 5] = s;
    __syncthreads();
    float mean;
    {
        float tot = 0.f;
        #pragma unroll
        for (int i = 0; i < 8; i++) tot += red[i];
        mean = tot * (1.f / 256.f);
    }
    __syncthreads();
    // variance (two-pass, matches mean((a-mu)^2))
    float d = a - mean;
    float s2 = d * d;
    #pragma unroll
    for (int o = 16; o > 0; o >>= 1) s2 += __shfl_xor_sync(0xffffffffu, s2, o);
    if ((t & 31) == 0) red[t >> 5] = s2;
    __syncthreads();
    float var;
    {
        float tot = 0.f;
        #pragma unroll
        for (int i = 0; i < 8; i++) tot += red[i];
        var = tot * (1.f / 256.f);
    }
    float norm = d * rsqrtf(var + 1e-3f) * gamma[t] + beta[t];
    g_g[(size_t)row * 256 + t] = g_u[(size_t)row * 256 + t] * norm;
}

// ---------------- kernel 5: final GEMM + relu + residual ----------------
// out = relu(g[8192,256] @ Wf[256,128] + bf) + x ; grid (2, 128)
__global__ void final_kernel(const float* __restrict__ x,
                             const float* __restrict__ Wf, const float* __restrict__ bf,
                             float* __restrict__ out)
{
    __shared__ float gs[64][33];
    __shared__ float ws[32][65];
    const int c0 = blockIdx.x * 64;
    const int r0 = blockIdx.y * 64;
    const int t  = threadIdx.x, tx = t & 15, ty = t >> 4;

    float acc[4][4] = {};

    for (int kc = 0; kc < 256; kc += 32) {
        #pragma unroll
        for (int i = t; i < 64*32; i += 256) {
            int rr = i >> 5, cc = i & 31;
            gs[rr][cc] = g_g[(size_t)(r0 + rr) * 256 + kc + cc];
        }
        #pragma unroll
        for (int i = t; i < 32*64; i += 256) {
            int rr = i >> 6, cc = i & 63;
            ws[rr][cc] = Wf[(kc + rr) * 128 + c0 + cc];
        }
        __syncthreads();
        #pragma unroll
        for (int kk = 0; kk < 32; kk++) {
            float av[4], bv2[4];
            #pragma unroll
            for (int i = 0; i < 4; i++) av[i] = gs[ty*4 + i][kk];
            #pragma unroll
            for (int j = 0; j < 4; j++) bv2[j] = ws[kk][tx*4 + j];
            #pragma unroll
            for (int i = 0; i < 4; i++)
                #pragma unroll
                for (int j = 0; j < 4; j++)
                    acc[i][j] = fmaf(av[i], bv2[j], acc[i][j]);
        }
        __syncthreads();
    }

    #pragma unroll
    for (int i = 0; i < 4; i++) {
        int rr = r0 + ty*4 + i;
        #pragma unroll
        for (int j = 0; j < 4; j++) {
            int cc = c0 + tx*4 + j;
            float v = acc[i][j] + bf[cc];
            v = fmaxf(v, 0.f) + x[(size_t)rr * 128 + cc];
            out[(size_t)rr * 128 + cc] = v;
        }
    }
}

// ---------------- launcher ----------------
extern "C" void kernel_launch(void* const* d_in, const int* in_sizes, int n_in,
                              void* d_out, int out_size)
{
    const float* x      = (const float*)d_in[0];
    const float* Wq     = (const float*)d_in[1];
    const float* bq     = (const float*)d_in[2];
    const float* Wk     = (const float*)d_in[3];
    const float* bk     = (const float*)d_in[4];
    const float* Wv     = (const float*)d_in[5];
    const float* bv     = (const float*)d_in[6];
    const float* Wu     = (const float*)d_in[7];
    const float* bu     = (const float*)d_in[8];
    const float* pos_w  = (const float*)d_in[9];
    const float* gamma  = (const float*)d_in[10];
    const float* beta   = (const float*)d_in[11];
    const float* Wf     = (const float*)d_in[12];
    const float* bf     = (const float*)d_in[13];
    float* out = (float*)d_out;

    proj_kernel<<<dim3(10, ROWS/64), 256>>>(x, Wq, bq, Wk, bk, Wv, bv, Wu, bu);
    attn_kernel<<<dim3(SEQ/64, BATCH*4), 256>>>();
    pos_kernel<<<dim3(SEQ/64, 2, BATCH), 256>>>(pos_w);
    ln_kernel<<<ROWS, 256>>>(gamma, beta);
    final_kernel<<<dim3(2, ROWS/64), 256>>>(x, Wf, bf, out);
}

// round 2
// speedup vs baseline: 1.7322x; 1.7322x over previous
#include <cuda_runtime.h>
#include <math.h>

#define BATCH 4
#define SEQ   2048
#define DIM   128
#define ROWS  (BATCH*SEQ)   // 8192

typedef unsigned long long ull;

// ---------------- scratch (no allocation allowed) ----------------
__device__ float g_q[ROWS*DIM];
__device__ float g_k[ROWS*DIM];
__device__ float g_v[ROWS*DIM];
__device__ float g_u[ROWS*2*DIM];
__device__ float g_sattn[ROWS*DIM];
__device__ float g_pattn[ROWS*DIM];
__device__ float g_g[ROWS*2*DIM];

__device__ __forceinline__ float silu_f(float v) {
    // v / (1 + e^-v) using fast exp (MUFU)
    return v * (1.f / (1.f + __expf(-v)));
}

__device__ __forceinline__ ull pack2(float lo, float hi) {
    ull r;
    asm("mov.b64 %0, {%1, %2};" : "=l"(r) : "r"(__float_as_uint(lo)), "r"(__float_as_uint(hi)));
    return r;
}
__device__ __forceinline__ ull fma2(ull a, ull b, ull c) {
    ull d;
    asm("fma.rn.f32x2 %0, %1, %2, %3;" : "=l"(d) : "l"(a), "l"(b), "l"(c));
    return d;
}
__device__ __forceinline__ float2 unpack2(ull v) {
    unsigned lo, hi;
    asm("mov.b64 {%0, %1}, %2;" : "=r"(lo), "=r"(hi) : "l"(v));
    return make_float2(__uint_as_float(lo), __uint_as_float(hi));
}

// ---------------- kernel 1: fused q/k/v/u projections ----------------
// grid (5, 128): seg 0..2 -> q/k/v (128 cols), seg 3..4 -> u halves. Tile 64r x 128c.
__global__ __launch_bounds__(256) void proj_kernel(
    const float* __restrict__ x,
    const float* __restrict__ Wq, const float* __restrict__ bq,
    const float* __restrict__ Wk, const float* __restrict__ bk,
    const float* __restrict__ Wv, const float* __restrict__ bv,
    const float* __restrict__ Wu, const float* __restrict__ bu)
{
    __shared__ float xs[64][36];
    __shared__ float ws[32][128];

    const int seg = blockIdx.x;
    const int r0  = blockIdx.y * 64;

    const float* W; const float* bias; float* out; int ldw, c0; bool act;
    if (seg == 0)      { W = Wq; bias = bq; out = g_q; ldw = 128; c0 = 0;   act = true;  }
    else if (seg == 1) { W = Wk; bias = bk; out = g_k; ldw = 128; c0 = 0;   act = true;  }
    else if (seg == 2) { W = Wv; bias = bv; out = g_v; ldw = 128; c0 = 0;   act = true;  }
    else               { W = Wu; bias = bu; out = g_u; ldw = 256; c0 = (seg - 3) * 128; act = false; }

    const int t = threadIdx.x, ty = t >> 4, tx = t & 15;

    ull acc[4][4];
    #pragma unroll
    for (int i = 0; i < 4; i++)
        #pragma unroll
        for (int j = 0; j < 4; j++) acc[i][j] = 0ull;

    for (int kc = 0; kc < 128; kc += 32) {
        #pragma unroll
        for (int i = t; i < 64*32; i += 256) {
            int rr = i >> 5, cc = i & 31;
            xs[rr][cc] = x[(r0 + rr) * 128 + kc + cc];
        }
        #pragma unroll
        for (int i = t; i < 32*128; i += 256) {
            int rr = i >> 7, cc = i & 127;
            ws[rr][cc] = W[(kc + rr) * ldw + c0 + cc];
        }
        __syncthreads();

        #pragma unroll
        for (int kk = 0; kk < 32; kk += 4) {
            float4 a[4];
            #pragma unroll
            for (int i = 0; i < 4; i++)
                a[i] = *(const float4*)&xs[ty*4 + i][kk];
            #pragma unroll
            for (int q = 0; q < 4; q++) {
                ulonglong2 bA = *(const ulonglong2*)&ws[kk + q][tx*8];
                ulonglong2 bB = *(const ulonglong2*)&ws[kk + q][tx*8 + 4];
                ull bp0 = bA.x, bp1 = bA.y, bp2 = bB.x, bp3 = bB.y;
                #pragma unroll
                for (int i = 0; i < 4; i++) {
                    float av = (q == 0) ? a[i].x : (q == 1) ? a[i].y : (q == 2) ? a[i].z : a[i].w;
                    ull ap = pack2(av, av);
                    acc[i][0] = fma2(ap, bp0, acc[i][0]);
                    acc[i][1] = fma2(ap, bp1, acc[i][1]);
                    acc[i][2] = fma2(ap, bp2, acc[i][2]);
                    acc[i][3] = fma2(ap, bp3, acc[i][3]);
                }
            }
        }
        __syncthreads();
    }

    #pragma unroll
    for (int i = 0; i < 4; i++) {
        int row = r0 + ty*4 + i;
        float o[8];
        #pragma unroll
        for (int j = 0; j < 4; j++) {
            float2 p = unpack2(acc[i][j]);
            o[2*j] = p.x; o[2*j+1] = p.y;
        }
        #pragma unroll
        for (int j = 0; j < 8; j++) {
            int c = c0 + tx*8 + j;
            float v = o[j] + bias[c];
            if (act) v = silu_f(v);
            o[j] = v;
        }
        float4 s0 = make_float4(o[0], o[1], o[2], o[3]);
        float4 s1 = make_float4(o[4], o[5], o[6], o[7]);
        *(float4*)&out[row * ldw + c0 + tx*8]     = s0;
        *(float4*)&out[row * ldw + c0 + tx*8 + 4] = s1;
    }
}

// ---------------- kernel 2: causal attention with silu(masked s^2) ----------------
// grid (32, 16), 256 threads; blocks reversed so heavy causal tiles launch first.
__global__ __launch_bounds__(256) void attn_kernel()
{
    __shared__ float qs[64][36];
    __shared__ float ks[64][33];
    __shared__ float vsm[64][34];
    __shared__ float ss[64][68];

    const int n0 = ((int)gridDim.x - 1 - (int)blockIdx.x) * 64;
    const int b  = blockIdx.y >> 2;
    const int h  = blockIdx.y & 3;
    const int t  = threadIdx.x, ty = t >> 4, tx = t & 15;

    const float* qp = g_q + (b * SEQ) * 128 + h * 32;
    const float* kp = g_k + (b * SEQ) * 128 + h * 32;
    const float* vp = g_v + (b * SEQ) * 128 + h * 32;
    const float scale = 0.17677669529663687f;  // 1/sqrt(32)

    #pragma unroll
    for (int i = t; i < 64*32; i += 256) {
        int rr = i >> 5, cc = i & 31;
        qs[rr][cc] = qp[(n0 + rr) * 128 + cc];
    }

    ull acc2[4] = {0ull, 0ull, 0ull, 0ull};   // rows ty*4+i, cols 2tx..2tx+1

    for (int m0 = 0; m0 <= n0; m0 += 64) {
        #pragma unroll
        for (int i = t; i < 64*32; i += 256) {
            int rr = i >> 5, cc = i & 31;
            ks[rr][cc]  = kp[(m0 + rr) * 128 + cc];
            vsm[rr][cc] = vp[(m0 + rr) * 128 + cc];
        }
        __syncthreads();

        // ---- stage 1: scores 64x64 (rows 4ty+i, cols 4tx + 2*j2 + e)
        ull sacc[4][2];
        #pragma unroll
        for (int i = 0; i < 4; i++) { sacc[i][0] = 0ull; sacc[i][1] = 0ull; }

        #pragma unroll
        for (int kk = 0; kk < 32; kk += 4) {
            float4 a[4];
            #pragma unroll
            for (int i = 0; i < 4; i++)
                a[i] = *(const float4*)&qs[ty*4 + i][kk];
            #pragma unroll
            for (int q = 0; q < 4; q++) {
                float k0 = ks[tx*4 + 0][kk + q];
                float k1 = ks[tx*4 + 1][kk + q];
                float k2 = ks[tx*4 + 2][kk + q];
                float k3 = ks[tx*4 + 3][kk + q];
                ull kp0 = pack2(k0, k1);
                ull kp1 = pack2(k2, k3);
                #pragma unroll
                for (int i = 0; i < 4; i++) {
                    float av = (q == 0) ? a[i].x : (q == 1) ? a[i].y : (q == 2) ? a[i].z : a[i].w;
                    ull ap = pack2(av, av);
                    sacc[i][0] = fma2(ap, kp0, sacc[i][0]);
                    sacc[i][1] = fma2(ap, kp1, sacc[i][1]);
                }
            }
        }

        // mask + square + silu -> ss (row-major, float4 stores)
        #pragma unroll
        for (int i = 0; i < 4; i++) {
            int n = n0 + ty*4 + i;
            float2 p0 = unpack2(sacc[i][0]);
            float2 p1 = unpack2(sacc[i][1]);
            float sv[4] = {p0.x, p0.y, p1.x, p1.y};
            float w[4];
            #pragma unroll
            for (int j = 0; j < 4; j++) {
                int m = m0 + tx*4 + j;
                float s  = sv[j] * scale;
                float sq = (m <= n) ? s * s : 0.f;
                w[j] = silu_f(sq);
            }
            *(float4*)&ss[ty*4 + i][tx*4] = make_float4(w[0], w[1], w[2], w[3]);
        }
        __syncthreads();

        // ---- stage 2: acc += ss @ v  (rows 4ty+i, col pair 2tx)
        #pragma unroll
        for (int mm = 0; mm < 64; mm += 4) {
            float4 sf[4];
            #pragma unroll
            for (int i = 0; i < 4; i++)
                sf[i] = *(const float4*)&ss[ty*4 + i][mm];
            #pragma unroll
            for (int q = 0; q < 4; q++) {
                ull vpair = *(const ull*)&vsm[mm + q][tx*2];
                #pragma unroll
                for (int i = 0; i < 4; i++) {
                    float sv = (q == 0) ? sf[i].x : (q == 1) ? sf[i].y : (q == 2) ? sf[i].z : sf[i].w;
                    ull sp = pack2(sv, sv);
                    acc2[i] = fma2(sp, vpair, acc2[i]);
                }
            }
        }
        __syncthreads();
    }

    #pragma unroll
    for (int i = 0; i < 4; i++) {
        float2 r = unpack2(acc2[i]);
        int n = n0 + ty*4 + i;
        *(float2*)&g_sattn[(b * SEQ + n) * 128 + h * 32 + tx*2] = r;
    }
}

// ---------------- kernel 3: relative-position attention ----------------
// pos_attn[b,n,d] = sum_m pos_w[S-1+m-n] * v[b,m,d]; grid (32, 2, 4)
__global__ __launch_bounds__(256) void pos_kernel(const float* __restrict__ pos_w)
{
    __shared__ float vsm[64][68];
    __shared__ float sw[128];

    const int n0 = blockIdx.x * 64;
    const int d0 = blockIdx.y * 64;
    const int b  = blockIdx.z;
    const int t  = threadIdx.x, ty = t >> 4, tx = t & 15;

    ull acc[4][2];
    #pragma unroll
    for (int a = 0; a < 4; a++) { acc[a][0] = 0ull; acc[a][1] = 0ull; }

    for (int m0 = 0; m0 < SEQ; m0 += 64) {
        #pragma unroll
        for (int i = t; i < 64*64; i += 256) {
            int rr = i >> 6, cc = i & 63;
            vsm[rr][cc] = g_v[(b * SEQ + m0 + rr) * 128 + d0 + cc];
        }
        if (t < 127) sw[t] = pos_w[(SEQ - 1) + m0 - n0 - 63 + t];
        __syncthreads();

        #pragma unroll
        for (int j0 = 0; j0 < 64; j0 += 4) {
            float4 f0 = *(const float4*)&sw[j0 + 60 - ty*4];
            float4 f1 = *(const float4*)&sw[j0 + 64 - ty*4];
            float f[8] = {f0.x, f0.y, f0.z, f0.w, f1.x, f1.y, f1.z, f1.w};
            #pragma unroll
            for (int q = 0; q < 4; q++) {
                ulonglong2 vv = *(const ulonglong2*)&vsm[j0 + q][tx*4];
                #pragma unroll
                for (int a = 0; a < 4; a++) {
                    // w = sw[(j0+q) - (ty*4+a) + 63]; offset into f = q - a + 3 in [0,6]
                    float wv = f[q - a + 3];
                    ull wp = pack2(wv, wv);
                    acc[a][0] = fma2(wp, vv.x, acc[a][0]);
                    acc[a][1] = fma2(wp, vv.y, acc[a][1]);
                }
            }
        }
        __syncthreads();
    }

    #pragma unroll
    for (int a = 0; a < 4; a++) {
        int n = n0 + ty*4 + a;
        float2 p0 = unpack2(acc[a][0]);
        float2 p1 = unpack2(acc[a][1]);
        *(float4*)&g_pattn[(b * SEQ + n) * 128 + d0 + tx*4] =
            make_float4(p0.x, p0.y, p1.x, p1.y);
    }
}

// ---------------- kernel 4: LayerNorm(concat)*gamma+beta, times u ----------------
// warp per row; grid ROWS/8, 256 threads
__global__ __launch_bounds__(256) void ln_kernel(const float* __restrict__ gamma,
                                                 const float* __restrict__ beta)
{
    const int w = threadIdx.x >> 5, l = threadIdx.x & 31;
    const int row = blockIdx.x * 8 + w;

    float4 sa = *(const float4*)&g_sattn[row * 128 + l*4];
    float4 pa = *(const float4*)&g_pattn[row * 128 + l*4];

    float sum = sa.x + sa.y + sa.z + sa.w + pa.x + pa.y + pa.z + pa.w;
    #pragma unroll
    for (int o = 16; o > 0; o >>= 1) sum += __shfl_xor_sync(0xffffffffu, sum, o);
    float mean = sum * (1.f / 256.f);

    float dx0 = sa.x - mean, dx1 = sa.y - mean, dx2 = sa.z - mean, dx3 = sa.w - mean;
    float dy0 = pa.x - mean, dy1 = pa.y - mean, dy2 = pa.z - mean, dy3 = pa.w - mean;
    float s2 = dx0*dx0 + dx1*dx1 + dx2*dx2 + dx3*dx3
             + dy0*dy0 + dy1*dy1 + dy2*dy2 + dy3*dy3;
    #pragma unroll
    for (int o = 16; o > 0; o >>= 1) s2 += __shfl_xor_sync(0xffffffffu, s2, o);
    float r = rsqrtf(s2 * (1.f / 256.f) + 1e-3f);

    float4 ga0 = *(const float4*)&gamma[l*4];
    float4 be0 = *(const float4*)&beta[l*4];
    float4 ga1 = *(const float4*)&gamma[128 + l*4];
    float4 be1 = *(const float4*)&beta[128 + l*4];
    float4 u0  = *(const float4*)&g_u[row * 256 + l*4];
    float4 u1  = *(const float4*)&g_u[row * 256 + 128 + l*4];

    float4 o0, o1;
    o0.x = u0.x * (dx0 * r * ga0.x + be0.x);
    o0.y = u0.y * (dx1 * r * ga0.y + be0.y);
    o0.z = u0.z * (dx2 * r * ga0.z + be0.z);
    o0.w = u0.w * (dx3 * r * ga0.w + be0.w);
    o1.x = u1.x * (dy0 * r * ga1.x + be1.x);
    o1.y = u1.y * (dy1 * r * ga1.y + be1.y);
    o1.z = u1.z * (dy2 * r * ga1.z + be1.z);
    o1.w = u1.w * (dy3 * r * ga1.w + be1.w);

    *(float4*)&g_g[row * 256 + l*4]       = o0;
    *(float4*)&g_g[row * 256 + 128 + l*4] = o1;
}

// ---------------- kernel 5: final GEMM + relu + residual ----------------
// out = relu(g[8192,256] @ Wf[256,128] + bf) + x ; tile 32r x 128c, grid 256
__global__ __launch_bounds__(256) void final_kernel(const float* __restrict__ x,
                                                    const float* __restrict__ Wf,
                                                    const float* __restrict__ bf,
                                                    float* __restrict__ out)
{
    __shared__ float gs[32][36];
    __shared__ float ws[32][128];

    const int r0 = blockIdx.x * 32;
    const int t  = threadIdx.x, ty = t >> 5, tx = t & 31;  // 8 row-groups x 32 col-groups

    ull acc[4][2];
    #pragma unroll
    for (int i = 0; i < 4; i++) { acc[i][0] = 0ull; acc[i][1] = 0ull; }

    for (int kc = 0; kc < 256; kc += 32) {
        #pragma unroll
        for (int i = t; i < 32*32; i += 256) {
            int rr = i >> 5, cc = i & 31;
            gs[rr][cc] = g_g[(r0 + rr) * 256 + kc + cc];
        }
        #pragma unroll
        for (int i = t; i < 32*128; i += 256) {
            int rr = i >> 7, cc = i & 127;
            ws[rr][cc] = Wf[(kc + rr) * 128 + cc];
        }
        __syncthreads();

        #pragma unroll
        for (int kk = 0; kk < 32; kk += 4) {
            float4 a[4];
            #pragma unroll
            for (int i = 0; i < 4; i++)
                a[i] = *(const float4*)&gs[ty*4 + i][kk];
            #pragma unroll
            for (int q = 0; q < 4; q++) {
                ulonglong2 bp = *(const ulonglong2*)&ws[kk + q][tx*4];
                #pragma unroll
                for (int i = 0; i < 4; i++) {
                    float av = (q == 0) ? a[i].x : (q == 1) ? a[i].y : (q == 2) ? a[i].z : a[i].w;
                    ull ap = pack2(av, av);
                    acc[i][0] = fma2(ap, bp.x, acc[i][0]);
                    acc[i][1] = fma2(ap, bp.y, acc[i][1]);
                }
            }
        }
        __syncthreads();
    }

    #pragma unroll
    for (int i = 0; i < 4; i++) {
        int row = r0 + ty*4 + i;
        float2 p0 = unpack2(acc[i][0]);
        float2 p1 = unpack2(acc[i][1]);
        float o[4] = {p0.x, p0.y, p1.x, p1.y};
        float4 xr = *(const float4*)&x[row * 128 + tx*4];
        float xv[4] = {xr.x, xr.y, xr.z, xr.w};
        float4 res;
        float* rp = (float*)&res;
        #pragma unroll
        for (int j = 0; j < 4; j++) {
            int c = tx*4 + j;
            rp[j] = fmaxf(o[j] + bf[c], 0.f) + xv[j];
        }
        *(float4*)&out[row * 128 + tx*4] = res;
    }
}

// ---------------- launcher ----------------
extern "C" void kernel_launch(void* const* d_in, const int* in_sizes, int n_in,
                              void* d_out, int out_size)
{
    const float* x      = (const float*)d_in[0];
    const float* Wq     = (const float*)d_in[1];
    const float* bq     = (const float*)d_in[2];
    const float* Wk     = (const float*)d_in[3];
    const float* bk     = (const float*)d_in[4];
    const float* Wv     = (const float*)d_in[5];
    const float* bv     = (const float*)d_in[6];
    const float* Wu     = (const float*)d_in[7];
    const float* bu     = (const float*)d_in[8];
    const float* pos_w  = (const float*)d_in[9];
    const float* gamma  = (const float*)d_in[10];
    const float* beta   = (const float*)d_in[11];
    const float* Wf     = (const float*)d_in[12];
    const float* bf     = (const float*)d_in[13];
    float* out = (float*)d_out;

    proj_kernel<<<dim3(5, ROWS/64), 256>>>(x, Wq, bq, Wk, bk, Wv, bv, Wu, bu);
    attn_kernel<<<dim3(SEQ/64, BATCH*4), 256>>>();
    pos_kernel<<<dim3(SEQ/64, 2, BATCH), 256>>>(pos_w);
    ln_kernel<<<ROWS/8, 256>>>(gamma, beta);
    final_kernel<<<ROWS/32, 256>>>(x, Wf, bf, out);
}

// round 3
// speedup vs baseline: 3.3512x; 1.9346x over previous
#include <cuda_runtime.h>
#include <math.h>

#define BATCH 4
#define SEQ   2048
#define DIM   128
#define ROWS  (BATCH*SEQ)   // 8192

typedef unsigned long long ull;
typedef unsigned int uint32;

// ---------------- scratch (no allocation allowed) ----------------
__device__ float g_q[ROWS*DIM];       // tf32-rounded
__device__ float g_k[ROWS*DIM];       // tf32-rounded
__device__ float g_v[ROWS*DIM];       // tf32-rounded
__device__ float g_u[ROWS*2*DIM];     // full f32
__device__ float g_sattn[ROWS*DIM];
__device__ float g_pattn[ROWS*DIM];
__device__ float g_g[ROWS*2*DIM];

__device__ __forceinline__ float silu_f(float v) {
    return v * (1.f / (1.f + __expf(-v)));
}
__device__ __forceinline__ uint32 tf32_of(float f) {
    uint32 u; asm("cvt.rna.tf32.f32 %0, %1;" : "=r"(u) : "f"(f)); return u;
}
__device__ __forceinline__ float tf32f(float f) { return __uint_as_float(tf32_of(f)); }

// D += A(16x8) * B(8x8), tf32 inputs as raw b32, f32 accum
__device__ __forceinline__ void mma_tf32(float4& d, uint32 a0, uint32 a1, uint32 a2, uint32 a3,
                                         uint32 b0, uint32 b1) {
    asm volatile(
        "mma.sync.aligned.m16n8k8.row.col.f32.tf32.tf32.f32 "
        "{%0,%1,%2,%3}, {%4,%5,%6,%7}, {%8,%9}, {%0,%1,%2,%3};"
        : "+f"(d.x), "+f"(d.y), "+f"(d.z), "+f"(d.w)
        : "r"(a0), "r"(a1), "r"(a2), "r"(a3), "r"(b0), "r"(b1));
}
__device__ __forceinline__ uint32 fb(float f) { return __float_as_uint(f); }

// ---------------- kernel 1: fused q/k/v/u projections (tf32 mma) ----------------
// grid (5, 128). Block tile: 64 rows x 128 cols. 8 warps = 4m x 2n, warp = m16 x n64.
__global__ __launch_bounds__(256) void proj_kernel(
    const float* __restrict__ x,
    const float* __restrict__ Wq, const float* __restrict__ bq,
    const float* __restrict__ Wk, const float* __restrict__ bk,
    const float* __restrict__ Wv, const float* __restrict__ bv,
    const float* __restrict__ Wu, const float* __restrict__ bu)
{
    __shared__ float xs[64][36];    // 32-k chunk of x (tf32-rounded)
    __shared__ float ws[32][136];   // 32-k chunk of W (tf32-rounded)

    const int seg = blockIdx.x;
    const int r0  = blockIdx.y * 64;

    const float* W; const float* bias; float* out; int ldw, c0; bool act;
    if (seg == 0)      { W = Wq; bias = bq; out = g_q; ldw = 128; c0 = 0;   act = true;  }
    else if (seg == 1) { W = Wk; bias = bk; out = g_k; ldw = 128; c0 = 0;   act = true;  }
    else if (seg == 2) { W = Wv; bias = bv; out = g_v; ldw = 128; c0 = 0;   act = true;  }
    else               { W = Wu; bias = bu; out = g_u; ldw = 256; c0 = (seg - 3) * 128; act = false; }

    const int t = threadIdx.x;
    const int w = t >> 5, lane = t & 31;
    const int wm = w & 3, wn = w >> 2;          // 4 x 2 warp grid
    const int g = lane >> 2, tg = lane & 3;

    float4 acc[8];
    #pragma unroll
    for (int j = 0; j < 8; j++) acc[j] = make_float4(0.f, 0.f, 0.f, 0.f);

    for (int kc = 0; kc < 128; kc += 32) {
        #pragma unroll
        for (int i = t*4; i < 64*32; i += 256*4) {
            int rr = i >> 5, cc = i & 31;
            float4 v4 = *(const float4*)&x[(r0 + rr) * 128 + kc + cc];
            xs[rr][cc+0] = tf32f(v4.x); xs[rr][cc+1] = tf32f(v4.y);
            xs[rr][cc+2] = tf32f(v4.z); xs[rr][cc+3] = tf32f(v4.w);
        }
        #pragma unroll
        for (int i = t*4; i < 32*128; i += 256*4) {
            int rr = i >> 7, cc = i & 127;
            float4 v4 = *(const float4*)&W[(kc + rr) * ldw + c0 + cc];
            ws[rr][cc+0] = tf32f(v4.x); ws[rr][cc+1] = tf32f(v4.y);
            ws[rr][cc+2] = tf32f(v4.z); ws[rr][cc+3] = tf32f(v4.w);
        }
        __syncthreads();

        #pragma unroll
        for (int kk = 0; kk < 32; kk += 8) {
            uint32 a0 = fb(xs[wm*16 + g    ][kk + tg    ]);
            uint32 a1 = fb(xs[wm*16 + g + 8][kk + tg    ]);
            uint32 a2 = fb(xs[wm*16 + g    ][kk + tg + 4]);
            uint32 a3 = fb(xs[wm*16 + g + 8][kk + tg + 4]);
            #pragma unroll
            for (int j = 0; j < 8; j++) {
                uint32 b0 = fb(ws[kk + tg    ][wn*64 + j*8 + g]);
                uint32 b1 = fb(ws[kk + tg + 4][wn*64 + j*8 + g]);
                mma_tf32(acc[j], a0, a1, a2, a3, b0, b1);
            }
        }
        __syncthreads();
    }

    #pragma unroll
    for (int j = 0; j < 8; j++) {
        int col = c0 + wn*64 + j*8 + 2*tg;
        float b0v = bias[col], b1v = bias[col + 1];
        int row0 = r0 + wm*16 + g;
        float v00 = acc[j].x + b0v, v01 = acc[j].y + b1v;
        float v10 = acc[j].z + b0v, v11 = acc[j].w + b1v;
        if (act) {
            v00 = tf32f(silu_f(v00)); v01 = tf32f(silu_f(v01));
            v10 = tf32f(silu_f(v10)); v11 = tf32f(silu_f(v11));
        }
        *(float2*)&out[row0 * ldw + col]       = make_float2(v00, v01);
        *(float2*)&out[(row0 + 8) * ldw + col] = make_float2(v10, v11);
    }
}

// ---------------- kernel 2: causal attention, tf32 mma both stages ----------------
// grid (32, 16), 256 threads = 8 warps (4m x 2n).
__global__ __launch_bounds__(256) void attn_kernel()
{
    __shared__ float qs [64][36];
    __shared__ float ks [64][36];
    __shared__ float vsm[64][40];
    __shared__ float ss [64][68];   // silu weights (tf32-rounded bits)

    const int n0 = ((int)gridDim.x - 1 - (int)blockIdx.x) * 64;
    const int b  = blockIdx.y >> 2;
    const int h  = blockIdx.y & 3;
    const int t  = threadIdx.x;
    const int w = t >> 5, lane = t & 31;
    const int wm = w & 3, wn = w >> 2;
    const int g = lane >> 2, tg = lane & 3;

    const float* qp = g_q + (b * SEQ) * 128 + h * 32;
    const float* kp = g_k + (b * SEQ) * 128 + h * 32;
    const float* vp = g_v + (b * SEQ) * 128 + h * 32;
    const float scale = 0.17677669529663687f;  // 1/sqrt(32)

    #pragma unroll
    for (int i = t*4; i < 64*32; i += 256*4) {
        int rr = i >> 5, cc = i & 31;
        *(float4*)&qs[rr][cc] = *(const float4*)&qp[(n0 + rr) * 128 + cc];
    }

    float4 oa[2];
    oa[0] = make_float4(0.f, 0.f, 0.f, 0.f);
    oa[1] = make_float4(0.f, 0.f, 0.f, 0.f);

    for (int m0 = 0; m0 <= n0; m0 += 64) {
        #pragma unroll
        for (int i = t*4; i < 64*32; i += 256*4) {
            int rr = i >> 5, cc = i & 31;
            *(float4*)&ks[rr][cc]  = *(const float4*)&kp[(m0 + rr) * 128 + cc];
            *(float4*)&vsm[rr][cc] = *(const float4*)&vp[(m0 + rr) * 128 + cc];
        }
        __syncthreads();

        // ---- stage 1: scores (warp tile m16 x n32 over keys)
        float4 sc[4];
        #pragma unroll
        for (int j = 0; j < 4; j++) sc[j] = make_float4(0.f, 0.f, 0.f, 0.f);

        #pragma unroll
        for (int kk = 0; kk < 32; kk += 8) {
            uint32 a0 = fb(qs[wm*16 + g    ][kk + tg    ]);
            uint32 a1 = fb(qs[wm*16 + g + 8][kk + tg    ]);
            uint32 a2 = fb(qs[wm*16 + g    ][kk + tg + 4]);
            uint32 a3 = fb(qs[wm*16 + g + 8][kk + tg + 4]);
            #pragma unroll
            for (int j = 0; j < 4; j++) {
                uint32 b0 = fb(ks[wn*32 + j*8 + g][kk + tg    ]);
                uint32 b1 = fb(ks[wn*32 + j*8 + g][kk + tg + 4]);
                mma_tf32(sc[j], a0, a1, a2, a3, b0, b1);
            }
        }

        // mask + square + silu -> ss (tf32)
        #pragma unroll
        for (int j = 0; j < 4; j++) {
            int r0 = n0 + wm*16 + g, r1 = r0 + 8;
            int cbase = m0 + wn*32 + j*8 + 2*tg;
            float s;
            s = sc[j].x * scale; s = (cbase     <= r0) ? s*s : 0.f; float w00 = silu_f(s);
            s = sc[j].y * scale; s = (cbase + 1 <= r0) ? s*s : 0.f; float w01 = silu_f(s);
            s = sc[j].z * scale; s = (cbase     <= r1) ? s*s : 0.f; float w10 = silu_f(s);
            s = sc[j].w * scale; s = (cbase + 1 <= r1) ? s*s : 0.f; float w11 = silu_f(s);
            int lr = wm*16 + g, lc = wn*32 + j*8 + 2*tg;
            ss[lr    ][lc    ] = tf32f(w00);
            ss[lr    ][lc + 1] = tf32f(w01);
            ss[lr + 8][lc    ] = tf32f(w10);
            ss[lr + 8][lc + 1] = tf32f(w11);
        }
        __syncthreads();

        // ---- stage 2: out += ss @ v (warp tile m16 x d16)
        #pragma unroll
        for (int kk = 0; kk < 64; kk += 8) {
            uint32 a0 = fb(ss[wm*16 + g    ][kk + tg    ]);
            uint32 a1 = fb(ss[wm*16 + g + 8][kk + tg    ]);
            uint32 a2 = fb(ss[wm*16 + g    ][kk + tg + 4]);
            uint32 a3 = fb(ss[wm*16 + g + 8][kk + tg + 4]);
            #pragma unroll
            for (int j = 0; j < 2; j++) {
                uint32 b0 = fb(vsm[kk + tg    ][wn*16 + j*8 + g]);
                uint32 b1 = fb(vsm[kk + tg + 4][wn*16 + j*8 + g]);
                mma_tf32(oa[j], a0, a1, a2, a3, b0, b1);
            }
        }
        __syncthreads();
    }

    #pragma unroll
    for (int j = 0; j < 2; j++) {
        int row0 = n0 + wm*16 + g;
        int col  = h*32 + wn*16 + j*8 + 2*tg;
        *(float2*)&g_sattn[(b * SEQ + row0) * 128 + col]     = make_float2(oa[j].x, oa[j].y);
        *(float2*)&g_sattn[(b * SEQ + row0 + 8) * 128 + col] = make_float2(oa[j].z, oa[j].w);
    }
}

// ---------------- kernel 3: relative-position attention (tf32 mma, Toeplitz A) ----------------
// grid (32, 2, 4): n-tile 64, d-tile 64, batch. Warp tile: n16 x d32.
__global__ __launch_bounds__(256) void pos_kernel(const float* __restrict__ pos_w)
{
    __shared__ float vsm[64][72];
    __shared__ float sw[128];

    const int n0 = blockIdx.x * 64;
    const int d0 = blockIdx.y * 64;
    const int b  = blockIdx.z;
    const int t  = threadIdx.x;
    const int w = t >> 5, lane = t & 31;
    const int wm = w & 3, wn = w >> 2;
    const int g = lane >> 2, tg = lane & 3;

    float4 acc[4];
    #pragma unroll
    for (int j = 0; j < 4; j++) acc[j] = make_float4(0.f, 0.f, 0.f, 0.f);

    for (int m0 = 0; m0 < SEQ; m0 += 64) {
        #pragma unroll
        for (int i = t*4; i < 64*64; i += 256*4) {
            int rr = i >> 6, cc = i & 63;
            *(float4*)&vsm[rr][cc] = *(const float4*)&g_v[(b * SEQ + m0 + rr) * 128 + d0 + cc];
        }
        if (t < 127) sw[t] = tf32f(pos_w[(SEQ - 1) + m0 - n0 - 63 + t]);
        __syncthreads();

        const int abase = 63 - wm*16 - g;
        #pragma unroll
        for (int kk = 0; kk < 64; kk += 8) {
            uint32 a0 = fb(sw[abase + kk + tg    ]);
            uint32 a1 = fb(sw[abase + kk + tg - 8]);
            uint32 a2 = fb(sw[abase + kk + tg + 4]);
            uint32 a3 = fb(sw[abase + kk + tg - 4]);
            #pragma unroll
            for (int j = 0; j < 4; j++) {
                uint32 b0 = fb(vsm[kk + tg    ][wn*32 + j*8 + g]);
                uint32 b1 = fb(vsm[kk + tg + 4][wn*32 + j*8 + g]);
                mma_tf32(acc[j], a0, a1, a2, a3, b0, b1);
            }
        }
        __syncthreads();
    }

    #pragma unroll
    for (int j = 0; j < 4; j++) {
        int row0 = n0 + wm*16 + g;
        int col  = d0 + wn*32 + j*8 + 2*tg;
        *(float2*)&g_pattn[(b * SEQ + row0) * 128 + col]     = make_float2(acc[j].x, acc[j].y);
        *(float2*)&g_pattn[(b * SEQ + row0 + 8) * 128 + col] = make_float2(acc[j].z, acc[j].w);
    }
}

// ---------------- kernel 4: LayerNorm(concat)*gamma+beta, times u ----------------
__global__ __launch_bounds__(256) void ln_kernel(const float* __restrict__ gamma,
                                                 const float* __restrict__ beta)
{
    const int w = threadIdx.x >> 5, l = threadIdx.x & 31;
    const int row = blockIdx.x * 8 + w;

    float4 sa = *(const float4*)&g_sattn[row * 128 + l*4];
    float4 pa = *(const float4*)&g_pattn[row * 128 + l*4];

    float sum = sa.x + sa.y + sa.z + sa.w + pa.x + pa.y + pa.z + pa.w;
    #pragma unroll
    for (int o = 16; o > 0; o >>= 1) sum += __shfl_xor_sync(0xffffffffu, sum, o);
    float mean = sum * (1.f / 256.f);

    float dx0 = sa.x - mean, dx1 = sa.y - mean, dx2 = sa.z - mean, dx3 = sa.w - mean;
    float dy0 = pa.x - mean, dy1 = pa.y - mean, dy2 = pa.z - mean, dy3 = pa.w - mean;
    float s2 = dx0*dx0 + dx1*dx1 + dx2*dx2 + dx3*dx3
             + dy0*dy0 + dy1*dy1 + dy2*dy2 + dy3*dy3;
    #pragma unroll
    for (int o = 16; o > 0; o >>= 1) s2 += __shfl_xor_sync(0xffffffffu, s2, o);
    float r = rsqrtf(s2 * (1.f / 256.f) + 1e-3f);

    float4 ga0 = *(const float4*)&gamma[l*4];
    float4 be0 = *(const float4*)&beta[l*4];
    float4 ga1 = *(const float4*)&gamma[128 + l*4];
    float4 be1 = *(const float4*)&beta[128 + l*4];
    float4 u0  = *(const float4*)&g_u[row * 256 + l*4];
    float4 u1  = *(const float4*)&g_u[row * 256 + 128 + l*4];

    float4 o0, o1;
    o0.x = u0.x * (dx0 * r * ga0.x + be0.x);
    o0.y = u0.y * (dx1 * r * ga0.y + be0.y);
    o0.z = u0.z * (dx2 * r * ga0.z + be0.z);
    o0.w = u0.w * (dx3 * r * ga0.w + be0.w);
    o1.x = u1.x * (dy0 * r * ga1.x + be1.x);
    o1.y = u1.y * (dy1 * r * ga1.y + be1.y);
    o1.z = u1.z * (dy2 * r * ga1.z + be1.z);
    o1.w = u1.w * (dy3 * r * ga1.w + be1.w);

    *(float4*)&g_g[row * 256 + l*4]       = o0;
    *(float4*)&g_g[row * 256 + 128 + l*4] = o1;
}

// ---------------- kernel 5: final GEMM + relu + residual (f32x2 SIMT, full precision) ----------------
typedef unsigned long long ull_t;
__device__ __forceinline__ ull_t pack2(float lo, float hi) {
    ull_t r;
    asm("mov.b64 %0, {%1, %2};" : "=l"(r) : "r"(__float_as_uint(lo)), "r"(__float_as_uint(hi)));
    return r;
}
__device__ __forceinline__ ull_t fma2(ull_t a, ull_t b, ull_t c) {
    ull_t d;
    asm("fma.rn.f32x2 %0, %1, %2, %3;" : "=l"(d) : "l"(a), "l"(b), "l"(c));
    return d;
}
__device__ __forceinline__ float2 unpack2(ull_t v) {
    unsigned lo, hi;
    asm("mov.b64 {%0, %1}, %2;" : "=r"(lo), "=r"(hi) : "l"(v));
    return make_float2(__uint_as_float(lo), __uint_as_float(hi));
}

__global__ __launch_bounds__(256) void final_kernel(const float* __restrict__ x,
                                                    const float* __restrict__ Wf,
                                                    const float* __restrict__ bf,
                                                    float* __restrict__ out)
{
    __shared__ float gs[32][36];
    __shared__ float ws[32][128];

    const int r0 = blockIdx.x * 32;
    const int t  = threadIdx.x, ty = t >> 5, tx = t & 31;

    ull_t acc[4][2];
    #pragma unroll
    for (int i = 0; i < 4; i++) { acc[i][0] = 0ull; acc[i][1] = 0ull; }

    for (int kc = 0; kc < 256; kc += 32) {
        #pragma unroll
        for (int i = t; i < 32*32; i += 256) {
            int rr = i >> 5, cc = i & 31;
            gs[rr][cc] = g_g[(r0 + rr) * 256 + kc + cc];
        }
        #pragma unroll
        for (int i = t; i < 32*128; i += 256) {
            int rr = i >> 7, cc = i & 127;
            ws[rr][cc] = Wf[(kc + rr) * 128 + cc];
        }
        __syncthreads();

        #pragma unroll
        for (int kk = 0; kk < 32; kk += 4) {
            float4 a[4];
            #pragma unroll
            for (int i = 0; i < 4; i++)
                a[i] = *(const float4*)&gs[ty*4 + i][kk];
            #pragma unroll
            for (int q = 0; q < 4; q++) {
                ulonglong2 bp = *(const ulonglong2*)&ws[kk + q][tx*4];
                #pragma unroll
                for (int i = 0; i < 4; i++) {
                    float av = (q == 0) ? a[i].x : (q == 1) ? a[i].y : (q == 2) ? a[i].z : a[i].w;
                    ull_t ap = pack2(av, av);
                    acc[i][0] = fma2(ap, bp.x, acc[i][0]);
                    acc[i][1] = fma2(ap, bp.y, acc[i][1]);
                }
            }
        }
        __syncthreads();
    }

    #pragma unroll
    for (int i = 0; i < 4; i++) {
        int row = r0 + ty*4 + i;
        float2 p0 = unpack2(acc[i][0]);
        float2 p1 = unpack2(acc[i][1]);
        float o[4] = {p0.x, p0.y, p1.x, p1.y};
        float4 xr = *(const float4*)&x[row * 128 + tx*4];
        float xv[4] = {xr.x, xr.y, xr.z, xr.w};
        float4 res;
        float* rp = (float*)&res;
        #pragma unroll
        for (int j = 0; j < 4; j++) {
            int c = tx*4 + j;
            rp[j] = fmaxf(o[j] + bf[c], 0.f) + xv[j];
        }
        *(float4*)&out[row * 128 + tx*4] = res;
    }
}

// ---------------- launcher ----------------
extern "C" void kernel_launch(void* const* d_in, const int* in_sizes, int n_in,
                              void* d_out, int out_size)
{
    const float* x      = (const float*)d_in[0];
    const float* Wq     = (const float*)d_in[1];
    const float* bq     = (const float*)d_in[2];
    const float* Wk     = (const float*)d_in[3];
    const float* bk     = (const float*)d_in[4];
    const float* Wv     = (const float*)d_in[5];
    const float* bv     = (const float*)d_in[6];
    const float* Wu     = (const float*)d_in[7];
    const float* bu     = (const float*)d_in[8];
    const float* pos_w  = (const float*)d_in[9];
    const float* gamma  = (const float*)d_in[10];
    const float* beta   = (const float*)d_in[11];
    const float* Wf     = (const float*)d_in[12];
    const float* bf     = (const float*)d_in[13];
    float* out = (float*)d_out;

    proj_kernel<<<dim3(5, ROWS/64), 256>>>(x, Wq, bq, Wk, bk, Wv, bv, Wu, bu);
    attn_kernel<<<dim3(SEQ/64, BATCH*4), 256>>>();
    pos_kernel<<<dim3(SEQ/64, 2, BATCH), 256>>>(pos_w);
    ln_kernel<<<ROWS/8, 256>>>(gamma, beta);
    final_kernel<<<ROWS/32, 256>>>(x, Wf, bf, out);
}